// round 1
// baseline (speedup 1.0000x reference)
#include <cuda_runtime.h>
#include <cstdint>

// ---------------------------------------------------------------------------
// OutputBlock: quantized conv(64->64,3x3) + PReLU + act-quant, then
//              quantized conv(64->3,3x3) + PReLU + act-quant.
// fp32 FFMA2 (fma.rn.f32x2) implicit-GEMM, smem-tiled.
// ---------------------------------------------------------------------------

#define IMG_H 256
#define IMG_W 256
#define NB    8
#define CIN   64
#define COUT2 3

// intermediate activation scratch (allowed: __device__ global array)
__device__ float g_h[NB * CIN * IMG_H * IMG_W];

// ---------------- conv1: 64 -> 64 -------------------------------------------
// tile: 8 rows x 32 cols of pixels, all 64 output channels per block.
// threads: 256 = 8 warps; warp w owns output channels [8w, 8w+8).
// each thread: 8 consecutive pixels in one row, 8 channels => 64 fp32 accs
// packed as 4 channel-pairs x 8 pixels (u64 f32x2).
#define TH   8
#define TW   32
#define CC   8          // input channels per smem chunk
#define PR   10         // patch rows  (TH + 2)
#define PCW  34         // patch cols  (TW + 2)
#define PW   35         // padded smem row stride (bank-conflict-free)

__global__ __launch_bounds__(256, 2)
void conv1_kernel(const float* __restrict__ x,
                  const float* __restrict__ w1,
                  const float* __restrict__ b1,
                  const float* __restrict__ alpha1,
                  const float* __restrict__ sw1,
                  const float* __restrict__ sa1)
{
    __shared__ __align__(16) float s_in[CC * PR * PW];   // 11.2 KB
    __shared__ __align__(16) float s_w[CC * 9 * 64];     // 18.4 KB

    const int tid = threadIdx.x;
    const int bid = blockIdx.x;            // 8 n * 32 ty * 8 tx = 2048
    const int tx  = bid & 7;
    const int ty  = (bid >> 3) & 31;
    const int n   = bid >> 8;
    const int x0  = tx * TW;
    const int y0  = ty * TH;

    const int pt  = tid & 31;              // pixel-thread within warp
    const int cg  = tid >> 5;              // warp id = channel group
    const int r   = pt & 7;                // tile row 0..7
    const int cb  = (pt >> 3) << 3;        // col base 0,8,16,24

    unsigned long long acc[4][8];
    #pragma unroll
    for (int i = 0; i < 4; ++i)
        #pragma unroll
        for (int j = 0; j < 8; ++j) acc[i][j] = 0ULL;

    for (int c0 = 0; c0 < CIN; c0 += CC) {
        __syncthreads();
        // ---- load input patch (with zero halo) ----
        for (int idx = tid; idx < CC * PR * PCW; idx += 256) {
            int c   = idx / (PR * PCW);
            int rem = idx - c * (PR * PCW);
            int row = rem / PCW;
            int col = rem - row * PCW;
            int gy  = y0 + row - 1;
            int gx  = x0 + col - 1;
            float v = 0.f;
            if ((unsigned)gy < (unsigned)IMG_H && (unsigned)gx < (unsigned)IMG_W)
                v = x[(((n * CIN + c0 + c) * IMG_H + gy) << 8) + gx];
            s_in[(c * PR + row) * PW + col] = v;
        }
        // ---- load + fake-quant weights: layout [(c*9+kh*3+kw)*64 + oc] ----
        for (int idx = tid; idx < CC * 9 * 64; idx += 256) {
            int oc = idx & 63;
            int k  = idx >> 6;              // c*9 + kk
            int c  = k / 9;
            int kk = k - c * 9;
            float w = w1[(oc * CIN + c0 + c) * 9 + kk];
            float s = sw1[oc];
            float q = rintf(w / s);
            q = fminf(fmaxf(q, -64.f), 63.f);
            s_w[idx] = q * s;
        }
        __syncthreads();

        #pragma unroll 1
        for (int c = 0; c < CC; ++c) {
            #pragma unroll
            for (int kh = 0; kh < 3; ++kh) {
                const float* rowp = &s_in[(c * PR + r + kh) * PW + cb];
                unsigned long long v2[10];
                #pragma unroll
                for (int i = 0; i < 10; ++i) {
                    unsigned int u = __float_as_uint(rowp[i]);
                    asm("mov.b64 %0, {%1, %1};" : "=l"(v2[i]) : "r"(u));
                }
                #pragma unroll
                for (int kw = 0; kw < 3; ++kw) {
                    const unsigned long long* wp = (const unsigned long long*)
                        &s_w[((c * 9 + kh * 3 + kw) << 6) + (cg << 3)];
                    unsigned long long w2[4];
                    #pragma unroll
                    for (int j = 0; j < 4; ++j) w2[j] = wp[j];
                    #pragma unroll
                    for (int cp = 0; cp < 4; ++cp)
                        #pragma unroll
                        for (int px = 0; px < 8; ++px)
                            asm("fma.rn.f32x2 %0, %1, %2, %0;"
                                : "+l"(acc[cp][px])
                                : "l"(w2[cp]), "l"(v2[px + kw]));
                }
            }
        }
    }

    // ---- epilogue: bias + PReLU + act fake-quant, store to g_h ----
    const int gy = y0 + r;
    const int gx = x0 + cb;
    #pragma unroll
    for (int cp = 0; cp < 4; ++cp) {
        float lo[8], hi[8];
        #pragma unroll
        for (int px = 0; px < 8; ++px) {
            unsigned int a, b;
            asm("mov.b64 {%0, %1}, %2;" : "=r"(a), "=r"(b) : "l"(acc[cp][px]));
            lo[px] = __uint_as_float(a);
            hi[px] = __uint_as_float(b);
        }
        #pragma unroll
        for (int half = 0; half < 2; ++half) {
            const float* v = half ? hi : lo;
            int oc = (cg << 3) + (cp << 1) + half;
            float bb = b1[oc], aa = alpha1[oc], ss = sa1[oc];
            float o[8];
            #pragma unroll
            for (int i = 0; i < 8; ++i) {
                float y = v[i] + bb;
                float p = (y >= 0.f) ? y : aa * y;
                float q = rintf(p / ss);
                q = fminf(fmaxf(q, -64.f), 63.f);
                o[i] = q * ss;
            }
            float4* p4 = reinterpret_cast<float4*>(
                &g_h[(((n * CIN + oc) * IMG_H + gy) << 8) + gx]);
            p4[0] = make_float4(o[0], o[1], o[2], o[3]);
            p4[1] = make_float4(o[4], o[5], o[6], o[7]);
        }
    }
}

// ---------------- conv2: 64 -> 3 --------------------------------------------
// tile: 16 rows x 128 cols; 256 threads, each: 8 px (4 pairs) x 3 out ch.
#define T2H   16
#define T2W   128
#define CC2   4
#define P2R   18
#define P2CW  130
#define P2W   134     // even (8B-aligned pairs), decent bank spread

__global__ __launch_bounds__(256, 2)
void conv2_kernel(const float* __restrict__ w2,
                  const float* __restrict__ b2,
                  const float* __restrict__ alpha2,
                  const float* __restrict__ sw2,
                  const float* __restrict__ sa2,
                  float* __restrict__ out)
{
    __shared__ __align__(16) float s_in[CC2 * P2R * P2W];      // 38.6 KB
    __shared__ __align__(16) unsigned long long s_wd[CC2 * 9 * 3]; // dup pairs

    const int tid = threadIdx.x;
    const int bid = blockIdx.x;             // 8 n * 16 ty * 2 tx = 256
    const int txb = bid & 1;
    const int ty  = (bid >> 1) & 15;
    const int n   = bid >> 5;
    const int x0  = txb * T2W;
    const int y0  = ty * T2H;

    const int r  = tid & 15;
    const int cb = (tid >> 4) << 3;         // 0..120

    unsigned long long acc[3][4];
    #pragma unroll
    for (int i = 0; i < 3; ++i)
        #pragma unroll
        for (int j = 0; j < 4; ++j) acc[i][j] = 0ULL;

    for (int c0 = 0; c0 < CIN; c0 += CC2) {
        __syncthreads();
        for (int idx = tid; idx < CC2 * P2R * P2CW; idx += 256) {
            int c   = idx / (P2R * P2CW);
            int rem = idx - c * (P2R * P2CW);
            int row = rem / P2CW;
            int col = rem - row * P2CW;
            int gy  = y0 + row - 1;
            int gx  = x0 + col - 1;
            float v = 0.f;
            if ((unsigned)gy < (unsigned)IMG_H && (unsigned)gx < (unsigned)IMG_W)
                v = g_h[(((n * CIN + c0 + c) * IMG_H + gy) << 8) + gx];
            s_in[(c * P2R + row) * P2W + col] = v;
        }
        if (tid < CC2 * 9 * 3) {
            int oc = tid % 3;
            int k  = tid / 3;                 // c*9 + kk
            int c  = k / 9;
            int kk = k - c * 9;
            float w = w2[(oc * CIN + c0 + c) * 9 + kk];
            float s = sw2[oc];
            float q = rintf(w / s);
            q = fminf(fmaxf(q, -64.f), 63.f);
            float wq = q * s;
            unsigned long long d;
            unsigned int u = __float_as_uint(wq);
            asm("mov.b64 %0, {%1, %1};" : "=l"(d) : "r"(u));
            s_wd[k * 3 + oc] = d;
        }
        __syncthreads();

        #pragma unroll 1
        for (int c = 0; c < CC2; ++c) {
            #pragma unroll
            for (int kh = 0; kh < 3; ++kh) {
                const float* rowp = &s_in[(c * P2R + r + kh) * P2W + cb];
                float2 f[5];
                #pragma unroll
                for (int j = 0; j < 5; ++j)
                    f[j] = ((const float2*)rowp)[j];
                unsigned long long va[3][4];
                #pragma unroll
                for (int j = 0; j < 4; ++j) {
                    unsigned int a0 = __float_as_uint(f[j].x);
                    unsigned int a1 = __float_as_uint(f[j].y);
                    unsigned int a2 = __float_as_uint(f[j + 1].x);
                    unsigned int a3 = __float_as_uint(f[j + 1].y);
                    asm("mov.b64 %0, {%1, %2};" : "=l"(va[0][j]) : "r"(a0), "r"(a1));
                    asm("mov.b64 %0, {%1, %2};" : "=l"(va[1][j]) : "r"(a1), "r"(a2));
                    asm("mov.b64 %0, {%1, %2};" : "=l"(va[2][j]) : "r"(a2), "r"(a3));
                }
                #pragma unroll
                for (int kw = 0; kw < 3; ++kw) {
                    #pragma unroll
                    for (int oc = 0; oc < 3; ++oc) {
                        unsigned long long wv = s_wd[(c * 9 + kh * 3 + kw) * 3 + oc];
                        #pragma unroll
                        for (int pp = 0; pp < 4; ++pp)
                            asm("fma.rn.f32x2 %0, %1, %2, %0;"
                                : "+l"(acc[oc][pp])
                                : "l"(wv), "l"(va[kw][pp]));
                    }
                }
            }
        }
    }

    // ---- epilogue ----
    const int gy = y0 + r;
    const int gx = x0 + cb;
    #pragma unroll
    for (int oc = 0; oc < 3; ++oc) {
        float v[8];
        #pragma unroll
        for (int pp = 0; pp < 4; ++pp) {
            unsigned int a, b;
            asm("mov.b64 {%0, %1}, %2;" : "=r"(a), "=r"(b) : "l"(acc[oc][pp]));
            v[2 * pp]     = __uint_as_float(a);
            v[2 * pp + 1] = __uint_as_float(b);
        }
        float bb = b2[oc], aa = alpha2[oc], ss = sa2[oc];
        float o[8];
        #pragma unroll
        for (int i = 0; i < 8; ++i) {
            float y = v[i] + bb;
            float p = (y >= 0.f) ? y : aa * y;
            float q = rintf(p / ss);
            q = fminf(fmaxf(q, -64.f), 63.f);
            o[i] = q * ss;
        }
        float4* p4 = reinterpret_cast<float4*>(
            &out[(((n * COUT2 + oc) * IMG_H + gy) << 8) + gx]);
        p4[0] = make_float4(o[0], o[1], o[2], o[3]);
        p4[1] = make_float4(o[4], o[5], o[6], o[7]);
    }
}

// ---------------------------------------------------------------------------
extern "C" void kernel_launch(void* const* d_in, const int* in_sizes, int n_in,
                              void* d_out, int out_size)
{
    const float* x      = (const float*)d_in[0];
    const float* w1     = (const float*)d_in[1];
    const float* b1     = (const float*)d_in[2];
    const float* w2     = (const float*)d_in[3];
    const float* b2     = (const float*)d_in[4];
    const float* alpha1 = (const float*)d_in[5];
    const float* alpha2 = (const float*)d_in[6];
    const float* sw1    = (const float*)d_in[7];
    const float* sw2    = (const float*)d_in[8];
    const float* sa1    = (const float*)d_in[9];
    const float* sa2    = (const float*)d_in[10];
    float* out = (float*)d_out;

    conv1_kernel<<<NB * 32 * 8, 256>>>(x, w1, b1, alpha1, sw1, sa1);
    conv2_kernel<<<NB * 16 * 2, 256>>>(w2, b2, alpha2, sw2, sa2, out);
}

// round 4
// speedup vs baseline: 1.2083x; 1.2083x over previous
#include <cuda_runtime.h>
#include <cstdint>

// ---------------------------------------------------------------------------
// OutputBlock: qconv(64->64,3x3)+PReLU+aq  ->  qconv(64->3,3x3)+PReLU+aq
// fp32 FFMA2 (fma.rn.f32x2) implicit-GEMM, smem-tiled.
// R4: fix conv2 weight-smem load (144 elems, 128 threads -> strided loop).
// ---------------------------------------------------------------------------

#define IMG_H 256
#define IMG_W 256
#define NB    8
#define CIN   64

// scratch (allowed: __device__ global arrays)
__device__ float g_h[NB * CIN * IMG_H * IMG_W];
__device__ float g_w1q[CIN * 9 * 64];      // [(c*9+kk)*64 + oc]
__device__ float g_w2q[CIN * 9 * 4];       // [(c*9+kk)*4 + oc], oc 3 real + 1 zero

// ---------------- weight pre-quantization (one-shot, tiny) ------------------
__global__ void prequant_kernel(const float* __restrict__ w1,
                                const float* __restrict__ sw1,
                                const float* __restrict__ w2,
                                const float* __restrict__ sw2)
{
    int idx = blockIdx.x * 256 + threadIdx.x;
    if (idx < CIN * 9 * 64) {
        int oc = idx & 63;
        int k  = idx >> 6;          // c*9 + kk
        int c  = k / 9;
        int kk = k - c * 9;
        float w = w1[(oc * CIN + c) * 9 + kk];
        float s = sw1[oc];
        float q = rintf(w / s);
        q = fminf(fmaxf(q, -64.f), 63.f);
        g_w1q[idx] = q * s;
    } else if (idx < CIN * 9 * 64 + CIN * 9 * 4) {
        int j  = idx - CIN * 9 * 64;
        int oc = j & 3;
        int k  = j >> 2;            // c*9 + kk
        int c  = k / 9;
        int kk = k - c * 9;
        float v = 0.f;
        if (oc < 3) {
            float w = w2[(oc * CIN + c) * 9 + kk];
            float s = sw2[oc];
            float q = rintf(w / s);
            q = fminf(fmaxf(q, -64.f), 63.f);
            v = q * s;
        }
        g_w2q[j] = v;
    }
}

// ---------------- conv1: 64 -> 64 -------------------------------------------
// tile 8 rows x 32 cols, all 64 oc per block; 256 thr = 8 warps;
// warp w owns oc [8w,8w+8); thread: 8 px x 4 oc-pairs (f32x2).
#define TH   8
#define TW   32
#define CC   8          // input channels per smem chunk (static smem cap)
#define PR   10
#define PCW  34
#define PW   35         // stride: 35 mod 32 = 3 -> 3r+8g conflict-free

__global__ __launch_bounds__(256, 2)
void conv1_kernel(const float* __restrict__ x,
                  const float* __restrict__ b1,
                  const float* __restrict__ alpha1,
                  const float* __restrict__ sa1)
{
    __shared__ __align__(16) float s_in[CC * PR * PW];   // 11.2 KB
    __shared__ __align__(16) float s_w[CC * 9 * 64];     // 18.4 KB

    const int tid = threadIdx.x;
    const int bid = blockIdx.x;            // 8n * 32ty * 8tx = 2048
    const int tx  = bid & 7;
    const int ty  = (bid >> 3) & 31;
    const int n   = bid >> 8;
    const int x0  = tx * TW;
    const int y0  = ty * TH;

    const int pt  = tid & 31;
    const int cg  = tid >> 5;              // warp id = oc group
    const int r   = pt & 7;
    const int cb  = (pt >> 3) << 3;        // 0,8,16,24

    unsigned long long acc[4][8];
    #pragma unroll
    for (int i = 0; i < 4; ++i)
        #pragma unroll
        for (int j = 0; j < 8; ++j) acc[i][j] = 0ULL;

    for (int c0 = 0; c0 < CIN; c0 += CC) {
        __syncthreads();
        // ---- input patch (zero halo) ----
        for (int idx = tid; idx < CC * PR * PCW; idx += 256) {
            int c   = idx / (PR * PCW);
            int rem = idx - c * (PR * PCW);
            int row = rem / PCW;
            int col = rem - row * PCW;
            int gy  = y0 + row - 1;
            int gx  = x0 + col - 1;
            float v = 0.f;
            if ((unsigned)gy < (unsigned)IMG_H && (unsigned)gx < (unsigned)IMG_W)
                v = x[(((n * CIN + c0 + c) * IMG_H + gy) << 8) + gx];
            s_in[(c * PR + row) * PW + col] = v;
        }
        // ---- prequantized weights: straight float4 copy ----
        {
            const float4* src = reinterpret_cast<const float4*>(g_w1q + c0 * 9 * 64);
            float4* dst = reinterpret_cast<float4*>(s_w);
            #pragma unroll
            for (int i = 0; i < (CC * 9 * 64 / 4 + 255) / 256; ++i) {
                int j = tid + i * 256;
                if (j < CC * 9 * 64 / 4) dst[j] = src[j];
            }
        }
        __syncthreads();

        #pragma unroll 1
        for (int c = 0; c < CC; ++c) {
            #pragma unroll
            for (int kh = 0; kh < 3; ++kh) {
                const float* rowp = &s_in[(c * PR + r + kh) * PW + cb];
                unsigned long long v2[10];
                #pragma unroll
                for (int i = 0; i < 10; ++i) {
                    unsigned int u = __float_as_uint(rowp[i]);
                    asm("mov.b64 %0, {%1, %1};" : "=l"(v2[i]) : "r"(u));
                }
                #pragma unroll
                for (int kw = 0; kw < 3; ++kw) {
                    const unsigned long long* wp = (const unsigned long long*)
                        &s_w[((c * 9 + kh * 3 + kw) << 6) + (cg << 3)];
                    unsigned long long w2r[4];
                    #pragma unroll
                    for (int j = 0; j < 4; ++j) w2r[j] = wp[j];
                    #pragma unroll
                    for (int cp = 0; cp < 4; ++cp)
                        #pragma unroll
                        for (int px = 0; px < 8; ++px)
                            asm("fma.rn.f32x2 %0, %1, %2, %0;"
                                : "+l"(acc[cp][px])
                                : "l"(w2r[cp]), "l"(v2[px + kw]));
                }
            }
        }
    }

    // ---- epilogue: bias + PReLU + act fake-quant -> g_h ----
    const int gy = y0 + r;
    const int gx = x0 + cb;
    #pragma unroll
    for (int cp = 0; cp < 4; ++cp) {
        float lo[8], hi[8];
        #pragma unroll
        for (int px = 0; px < 8; ++px) {
            unsigned int a, b;
            asm("mov.b64 {%0, %1}, %2;" : "=r"(a), "=r"(b) : "l"(acc[cp][px]));
            lo[px] = __uint_as_float(a);
            hi[px] = __uint_as_float(b);
        }
        #pragma unroll
        for (int half = 0; half < 2; ++half) {
            const float* v = half ? hi : lo;
            int oc = (cg << 3) + (cp << 1) + half;
            float bb = b1[oc], aa = alpha1[oc], ss = sa1[oc];
            float o[8];
            #pragma unroll
            for (int i = 0; i < 8; ++i) {
                float y = v[i] + bb;
                float p = (y >= 0.f) ? y : aa * y;
                float q = rintf(p / ss);
                q = fminf(fmaxf(q, -64.f), 63.f);
                o[i] = q * ss;
            }
            float4* p4 = reinterpret_cast<float4*>(
                &g_h[(((n * CIN + oc) * IMG_H + gy) << 8) + gx]);
            p4[0] = make_float4(o[0], o[1], o[2], o[3]);
            p4[1] = make_float4(o[4], o[5], o[6], o[7]);
        }
    }
}

// ---------------- conv2: 64 -> 3 (padded to 4) ------------------------------
// tile 8 rows x 128 cols; 128 thr = 4 warps; warp w covers cols [32w,32w+32).
// thread: 8 px x 2 oc-pairs (f32x2 over oc pairs, input dup'd).
#define T2W   128
#define CC2   4
#define P2R   10
#define P2CW  130
#define P2W   131       // 131 mod 32 = 3 -> conflict-free

__global__ __launch_bounds__(128, 6)
void conv2_kernel(const float* __restrict__ b2,
                  const float* __restrict__ alpha2,
                  const float* __restrict__ sa2,
                  float* __restrict__ out)
{
    __shared__ __align__(16) float s_in[CC2 * P2R * P2W];   // 21.0 KB
    __shared__ __align__(16) float s_w[CC2 * 9 * 4];        // 576 B

    const int tid = threadIdx.x;
    const int bid = blockIdx.x;            // 8n * 32ty * 2tx = 512
    const int tx  = bid & 1;
    const int ty  = (bid >> 1) & 31;
    const int n   = bid >> 6;
    const int x0  = tx * T2W;
    const int y0  = ty * TH;

    const int r    = tid & 7;
    const int g    = (tid >> 3) & 3;
    const int warp = tid >> 5;
    const int cb   = warp * 32 + g * 8;    // 0..120

    unsigned long long acc[2][8];
    #pragma unroll
    for (int i = 0; i < 2; ++i)
        #pragma unroll
        for (int j = 0; j < 8; ++j) acc[i][j] = 0ULL;

    for (int c0 = 0; c0 < CIN; c0 += CC2) {
        __syncthreads();
        for (int idx = tid; idx < CC2 * P2R * P2CW; idx += 128) {
            int c   = idx / (P2R * P2CW);
            int rem = idx - c * (P2R * P2CW);
            int row = rem / P2CW;
            int col = rem - row * P2CW;
            int gy  = y0 + row - 1;
            int gx  = x0 + col - 1;
            float v = 0.f;
            if ((unsigned)gy < (unsigned)IMG_H && (unsigned)gx < (unsigned)IMG_W)
                v = g_h[(((n * CIN + c0 + c) * IMG_H + gy) << 8) + gx];
            s_in[(c * P2R + row) * P2W + col] = v;
        }
        // FIX: 144 elements, 128 threads -> strided loop (was if(tid<144))
        for (int idx = tid; idx < CC2 * 9 * 4; idx += 128)
            s_w[idx] = g_w2q[c0 * 9 * 4 + idx];
        __syncthreads();

        #pragma unroll 1
        for (int c = 0; c < CC2; ++c) {
            #pragma unroll
            for (int kh = 0; kh < 3; ++kh) {
                const float* rowp = &s_in[(c * P2R + r + kh) * P2W + cb];
                unsigned long long v2[10];
                #pragma unroll
                for (int i = 0; i < 10; ++i) {
                    unsigned int u = __float_as_uint(rowp[i]);
                    asm("mov.b64 %0, {%1, %1};" : "=l"(v2[i]) : "r"(u));
                }
                #pragma unroll
                for (int kw = 0; kw < 3; ++kw) {
                    const unsigned long long* wp = (const unsigned long long*)
                        &s_w[(c * 9 + kh * 3 + kw) << 2];
                    unsigned long long w0 = wp[0];
                    unsigned long long w1 = wp[1];
                    #pragma unroll
                    for (int px = 0; px < 8; ++px) {
                        asm("fma.rn.f32x2 %0, %1, %2, %0;"
                            : "+l"(acc[0][px]) : "l"(w0), "l"(v2[px + kw]));
                        asm("fma.rn.f32x2 %0, %1, %2, %0;"
                            : "+l"(acc[1][px]) : "l"(w1), "l"(v2[px + kw]));
                    }
                }
            }
        }
    }

    // ---- epilogue ----
    const int gy = y0 + r;
    const int gx = x0 + cb;
    #pragma unroll
    for (int cp = 0; cp < 2; ++cp) {
        float lo[8], hi[8];
        #pragma unroll
        for (int px = 0; px < 8; ++px) {
            unsigned int a, b;
            asm("mov.b64 {%0, %1}, %2;" : "=r"(a), "=r"(b) : "l"(acc[cp][px]));
            lo[px] = __uint_as_float(a);
            hi[px] = __uint_as_float(b);
        }
        #pragma unroll
        for (int half = 0; half < 2; ++half) {
            int oc = (cp << 1) + half;
            if (oc >= 3) continue;
            const float* v = half ? hi : lo;
            float bb = b2[oc], aa = alpha2[oc], ss = sa2[oc];
            float o[8];
            #pragma unroll
            for (int i = 0; i < 8; ++i) {
                float y = v[i] + bb;
                float p = (y >= 0.f) ? y : aa * y;
                float q = rintf(p / ss);
                q = fminf(fmaxf(q, -64.f), 63.f);
                o[i] = q * ss;
            }
            float4* p4 = reinterpret_cast<float4*>(
                &out[(((n * 3 + oc) * IMG_H + gy) << 8) + gx]);
            p4[0] = make_float4(o[0], o[1], o[2], o[3]);
            p4[1] = make_float4(o[4], o[5], o[6], o[7]);
        }
    }
}

// ---------------------------------------------------------------------------
extern "C" void kernel_launch(void* const* d_in, const int* in_sizes, int n_in,
                              void* d_out, int out_size)
{
    const float* x      = (const float*)d_in[0];
    const float* w1     = (const float*)d_in[1];
    const float* b1     = (const float*)d_in[2];
    const float* w2     = (const float*)d_in[3];
    const float* b2     = (const float*)d_in[4];
    const float* alpha1 = (const float*)d_in[5];
    const float* alpha2 = (const float*)d_in[6];
    const float* sw1    = (const float*)d_in[7];
    const float* sw2    = (const float*)d_in[8];
    const float* sa1    = (const float*)d_in[9];
    const float* sa2    = (const float*)d_in[10];
    float* out = (float*)d_out;

    prequant_kernel<<<(CIN * 9 * 64 + CIN * 9 * 4 + 255) / 256, 256>>>(w1, sw1, w2, sw2);
    conv1_kernel<<<NB * 32 * 8, 256>>>(x, b1, alpha1, sa1);
    conv2_kernel<<<NB * 32 * 2, 128>>>(b2, alpha2, sa2, out);
}

// round 6
// speedup vs baseline: 1.9263x; 1.5942x over previous
#include <cuda_runtime.h>
#include <cuda_fp16.h>
#include <cstdint>

// ---------------------------------------------------------------------------
// R6: conv1 via warp-level mma.sync (HMMA, sm_80+ baseline — compiles on the
//     harness's plain sm_100 target). EXACT fp16 2-term activation split:
//     x = hi + lo (22 mantissa bits), weights are 7-bit ints (exact fp16),
//     fp32 accumulate => fp32-grade numerics at tensor-core rate.
//     conv2 stays fp32 FFMA2 (proven R4 kernel).
// ---------------------------------------------------------------------------

#define IMG   256
#define NB    8
#define CIN   64

__device__ float  g_h[NB * CIN * IMG * IMG];   // fp32 fake-quant intermediate
__device__ __half g_w1h[9 * 64 * 64];          // [tap][c(k)][oc] integer q in fp16
__device__ float  g_w2q[CIN * 9 * 4];          // conv2 fp32 wq

__device__ __forceinline__ uint32_t smem_u32(const void* p) {
    uint32_t a;
    asm("{ .reg .u64 t; cvta.to.shared.u64 t, %1; cvt.u32.u64 %0, t; }"
        : "=r"(a) : "l"(p));
    return a;
}

__device__ __forceinline__ void ldsm4(uint32_t* r, uint32_t addr) {
    asm volatile("ldmatrix.sync.aligned.m8n8.x4.shared.b16 {%0,%1,%2,%3}, [%4];"
        : "=r"(r[0]), "=r"(r[1]), "=r"(r[2]), "=r"(r[3]) : "r"(addr));
}
__device__ __forceinline__ void ldsm2t(uint32_t& r0, uint32_t& r1, uint32_t addr) {
    asm volatile("ldmatrix.sync.aligned.m8n8.x2.trans.shared.b16 {%0,%1}, [%2];"
        : "=r"(r0), "=r"(r1) : "r"(addr));
}
__device__ __forceinline__ void mma16816(float* c, const uint32_t* a, const uint32_t* b) {
    asm volatile("mma.sync.aligned.m16n8k16.row.col.f32.f16.f16.f32 "
        "{%0,%1,%2,%3}, {%4,%5,%6,%7}, {%8,%9}, {%0,%1,%2,%3};"
        : "+f"(c[0]), "+f"(c[1]), "+f"(c[2]), "+f"(c[3])
        : "r"(a[0]), "r"(a[1]), "r"(a[2]), "r"(a[3]), "r"(b[0]), "r"(b[1]));
}

// ---------------- prequant (one-shot) ---------------------------------------
__global__ void prequant_kernel(const float* __restrict__ w1,
                                const float* __restrict__ sw1,
                                const float* __restrict__ w2,
                                const float* __restrict__ sw2)
{
    int idx = blockIdx.x * 256 + threadIdx.x;
    if (idx < 9 * 64 * 64) {
        int oc  = idx & 63;
        int c   = (idx >> 6) & 63;
        int tap = idx >> 12;
        float w = w1[(oc * 64 + c) * 9 + tap];
        float s = sw1[oc];
        float q = rintf(w / s);
        q = fminf(fmaxf(q, -64.f), 63.f);
        g_w1h[idx] = __float2half_rn(q);        // exact 7-bit integer
    } else if (idx < 9 * 64 * 64 + 64 * 9 * 4) {
        int j  = idx - 9 * 64 * 64;
        int oc = j & 3;
        int k  = j >> 2;
        int c  = k / 9;
        int kk = k - c * 9;
        float v = 0.f;
        if (oc < 3) {
            float w = w2[(oc * CIN + c) * 9 + kk];
            float s = sw2[oc];
            float q = rintf(w / s);
            q = fminf(fmaxf(q, -64.f), 63.f);
            v = q * s;
        }
        g_w2q[j] = v;
    }
}

// ---------------- conv1: HMMA -----------------------------------------------
// CTA = 128-px row strip (n, y, x0), 64 oc. 256 thr = 8 warps.
// Warp tile: 32 px (mrow=(w&3)*32) x 32 oc (ncol=(w>>2)*32).
// A smem: [term][j=0..129][c=0..63] fp16, row stride 72 halves (144B).
// W smem: one tap [k=0..63][oc=0..63] fp16, row stride 72 halves (144B).
#define AROW   72            // halves per A/W row (144 B)
#define ATERM  (130 * AROW)  // halves per term strip

__global__ __launch_bounds__(256, 2)
void conv1_mma_kernel(const float* __restrict__ x,
                      const float* __restrict__ sw1,
                      const float* __restrict__ b1,
                      const float* __restrict__ alpha1,
                      const float* __restrict__ sa1)
{
    __shared__ __align__(16) __half s_a[2 * ATERM];   // 37440 B
    __shared__ __align__(16) __half s_w[64 * AROW];   //  9216 B
    __shared__ float s_prm[256];                      //  1024 B

    const int tid  = threadIdx.x;
    const int lane = tid & 31;
    const int warp = tid >> 5;
    const int mrow = (warp & 3) * 32;
    const int ncol = (warp >> 2) * 32;

    const int bid = blockIdx.x;          // 8n * 256y * 2xt = 4096
    const int x0  = (bid & 1) * 128;
    const int y   = (bid >> 1) & 255;
    const int n   = bid >> 9;

    if (tid < 256) {
        int a = tid >> 6, oc = tid & 63;
        const float* src = (a == 0) ? sw1 : (a == 1) ? b1 : (a == 2) ? alpha1 : sa1;
        s_prm[a * 64 + oc] = src[oc];
    }

    const uint32_t sa_base = smem_u32(s_a);
    const uint32_t sw_base = smem_u32(s_w);

    float acc[2][4][4];
    #pragma unroll
    for (int i = 0; i < 2; ++i)
        #pragma unroll
        for (int j = 0; j < 4; ++j)
            #pragma unroll
            for (int k = 0; k < 4; ++k) acc[i][j][k] = 0.f;

    const uint32_t arow = lane & 15;          // ldmatrix A row-within-16
    const uint32_t ahalf = (lane >> 4) * 16;  // byte offset of k-half

    for (int s = 0; s < 3; ++s) {
        const int gy = y + s - 1;
        const bool row_ok = (unsigned)gy < 256u;
        __syncthreads();                       // prior tap's A reads done
        // ---- build exact fp16 2-term split strip ----
        for (int idx = tid; idx < 64 * 130; idx += 256) {
            int c = idx / 130;
            int j = idx - c * 130;
            int gx = x0 - 1 + j;
            float v = 0.f;
            if (row_ok && (unsigned)gx < 256u)
                v = x[(((n * 64 + c) * 256 + gy) << 8) + gx];
            __half hi = __float2half_rn(v);
            __half lo = __float2half_rn(v - __half2float(hi));
            s_a[j * AROW + c]         = hi;
            s_a[ATERM + j * AROW + c] = lo;
        }

        for (int kw = 0; kw < 3; ++kw) {
            __syncthreads();                   // A ready / prior W reads done
            // ---- load this tap's weights (64x64 fp16 -> padded rows) ----
            {
                const uint4* src = reinterpret_cast<const uint4*>(
                    g_w1h + (s * 3 + kw) * 4096);
                for (int i = tid; i < 512; i += 256) {
                    int r = i >> 3, cs = i & 7;
                    reinterpret_cast<uint4*>(&s_w[r * AROW])[cs] = src[i];
                }
            }
            __syncthreads();                   // W ready

            // ---- B fragments (shared by both terms) ----
            uint32_t bf[4][4][2];
            #pragma unroll
            for (int k = 0; k < 4; ++k)
                #pragma unroll
                for (int nb = 0; nb < 4; ++nb)
                    ldsm2t(bf[k][nb][0], bf[k][nb][1],
                           sw_base + (k * 16 + (lane & 15)) * 144
                                   + (ncol + nb * 8) * 2);
            // ---- A fragments + MMA ----
            #pragma unroll
            for (int t = 0; t < 2; ++t) {
                #pragma unroll
                for (int mb = 0; mb < 2; ++mb) {
                    uint32_t af[4][4];
                    uint32_t abase = sa_base + t * (ATERM * 2)
                                   + (mrow + mb * 16 + arow + kw) * 144 + ahalf;
                    #pragma unroll
                    for (int k = 0; k < 4; ++k)
                        ldsm4(af[k], abase + k * 32);
                    #pragma unroll
                    for (int k = 0; k < 4; ++k)
                        #pragma unroll
                        for (int nb = 0; nb < 4; ++nb)
                            mma16816(acc[mb][nb], af[k], bf[k][nb]);
                }
            }
        }
    }

    // ---- epilogue: scale(sw1) + bias + PReLU + act fake-quant -> g_h -------
    #pragma unroll
    for (int mb = 0; mb < 2; ++mb)
        #pragma unroll
        for (int nb = 0; nb < 4; ++nb)
            #pragma unroll
            for (int rg = 0; rg < 4; ++rg) {
                int m  = mrow + mb * 16 + (lane >> 2) + (rg >> 1) * 8;
                int oc = ncol + nb * 8 + ((lane & 3) << 1) + (rg & 1);
                float v  = acc[mb][nb][rg] * s_prm[oc] + s_prm[64 + oc];
                float pv = (v >= 0.f) ? v : s_prm[128 + oc] * v;
                float ss = s_prm[192 + oc];
                float q  = rintf(pv / ss);
                q = fminf(fmaxf(q, -64.f), 63.f);
                g_h[(((n * 64 + oc) * 256 + y) << 8) + x0 + m] = q * ss;
            }
}

// ---------------- conv2: fp32 FFMA2 (proven R4 kernel, unchanged) -----------
#define TH2   8
#define T2W   128
#define CC2   4
#define P2R   10
#define P2CW  130
#define P2W   131

__global__ __launch_bounds__(128, 6)
void conv2_kernel(const float* __restrict__ b2,
                  const float* __restrict__ alpha2,
                  const float* __restrict__ sa2,
                  float* __restrict__ out)
{
    __shared__ __align__(16) float s_in[CC2 * P2R * P2W];
    __shared__ __align__(16) float s_w2[CC2 * 9 * 4];

    const int tid = threadIdx.x;
    const int bid = blockIdx.x;
    const int tx  = bid & 1;
    const int ty  = (bid >> 1) & 31;
    const int n   = bid >> 6;
    const int x0  = tx * T2W;
    const int y0  = ty * TH2;

    const int r    = tid & 7;
    const int g    = (tid >> 3) & 3;
    const int warp = tid >> 5;
    const int cb   = warp * 32 + g * 8;

    unsigned long long acc[2][8];
    #pragma unroll
    for (int i = 0; i < 2; ++i)
        #pragma unroll
        for (int j = 0; j < 8; ++j) acc[i][j] = 0ULL;

    for (int c0 = 0; c0 < CIN; c0 += CC2) {
        __syncthreads();
        for (int idx = tid; idx < CC2 * P2R * P2CW; idx += 128) {
            int c   = idx / (P2R * P2CW);
            int rem = idx - c * (P2R * P2CW);
            int row = rem / P2CW;
            int col = rem - row * P2CW;
            int gy  = y0 + row - 1;
            int gx  = x0 + col - 1;
            float v = 0.f;
            if ((unsigned)gy < 256u && (unsigned)gx < 256u)
                v = g_h[(((n * CIN + c0 + c) * 256 + gy) << 8) + gx];
            s_in[(c * P2R + row) * P2W + col] = v;
        }
        for (int idx = tid; idx < CC2 * 9 * 4; idx += 128)
            s_w2[idx] = g_w2q[c0 * 9 * 4 + idx];
        __syncthreads();

        #pragma unroll 1
        for (int c = 0; c < CC2; ++c) {
            #pragma unroll
            for (int kh = 0; kh < 3; ++kh) {
                const float* rowp = &s_in[(c * P2R + r + kh) * P2W + cb];
                unsigned long long v2[10];
                #pragma unroll
                for (int i = 0; i < 10; ++i) {
                    unsigned int u = __float_as_uint(rowp[i]);
                    asm("mov.b64 %0, {%1, %1};" : "=l"(v2[i]) : "r"(u));
                }
                #pragma unroll
                for (int kw = 0; kw < 3; ++kw) {
                    const unsigned long long* wp = (const unsigned long long*)
                        &s_w2[(c * 9 + kh * 3 + kw) << 2];
                    unsigned long long w0 = wp[0];
                    unsigned long long w1 = wp[1];
                    #pragma unroll
                    for (int px = 0; px < 8; ++px) {
                        asm("fma.rn.f32x2 %0, %1, %2, %0;"
                            : "+l"(acc[0][px]) : "l"(w0), "l"(v2[px + kw]));
                        asm("fma.rn.f32x2 %0, %1, %2, %0;"
                            : "+l"(acc[1][px]) : "l"(w1), "l"(v2[px + kw]));
                    }
                }
            }
        }
    }

    const int gy = y0 + r;
    const int gx = x0 + cb;
    #pragma unroll
    for (int cp = 0; cp < 2; ++cp) {
        float lo[8], hi[8];
        #pragma unroll
        for (int px = 0; px < 8; ++px) {
            unsigned int a, b;
            asm("mov.b64 {%0, %1}, %2;" : "=r"(a), "=r"(b) : "l"(acc[cp][px]));
            lo[px] = __uint_as_float(a);
            hi[px] = __uint_as_float(b);
        }
        #pragma unroll
        for (int half = 0; half < 2; ++half) {
            int oc = (cp << 1) + half;
            if (oc >= 3) continue;
            const float* v = half ? hi : lo;
            float bb = b2[oc], aa = alpha2[oc], ss = sa2[oc];
            float o[8];
            #pragma unroll
            for (int i = 0; i < 8; ++i) {
                float yv = v[i] + bb;
                float pv = (yv >= 0.f) ? yv : aa * yv;
                float q = rintf(pv / ss);
                q = fminf(fmaxf(q, -64.f), 63.f);
                o[i] = q * ss;
            }
            float4* p4 = reinterpret_cast<float4*>(
                &out[(((n * 3 + oc) * 256 + gy) << 8) + gx]);
            p4[0] = make_float4(o[0], o[1], o[2], o[3]);
            p4[1] = make_float4(o[4], o[5], o[6], o[7]);
        }
    }
}

// ---------------------------------------------------------------------------
extern "C" void kernel_launch(void* const* d_in, const int* in_sizes, int n_in,
                              void* d_out, int out_size)
{
    const float* x      = (const float*)d_in[0];
    const float* w1     = (const float*)d_in[1];
    const float* b1     = (const float*)d_in[2];
    const float* w2     = (const float*)d_in[3];
    const float* b2     = (const float*)d_in[4];
    const float* alpha1 = (const float*)d_in[5];
    const float* alpha2 = (const float*)d_in[6];
    const float* sw1    = (const float*)d_in[7];
    const float* sw2    = (const float*)d_in[8];
    const float* sa1    = (const float*)d_in[9];
    const float* sa2    = (const float*)d_in[10];
    float* out = (float*)d_out;

    prequant_kernel<<<(9 * 64 * 64 + 64 * 9 * 4 + 255) / 256, 256>>>(w1, sw1, w2, sw2);
    conv1_mma_kernel<<<NB * IMG * 2, 256>>>(x, sw1, b1, alpha1, sa1);
    conv2_kernel<<<NB * 32 * 2, 128>>>(b2, alpha2, sa2, out);
}